// round 14
// baseline (speedup 1.0000x reference)
#include <cuda_runtime.h>
#include <cuda_fp16.h>
#include <cstdint>

// Block-diagonal GEMM: single fused launch with producer/consumer CTA overlap.
//   bids [0, NCONV)      : converter CTAs — x fp32 -> fp16 slab-by-slab (kb order),
//                          publish done[kb] via threadfence + atomicAdd.
//   bids [NCONV, +4096)  : R5-proven 128x128 fp16 mma.sync GEMM CTAs (kb-major order),
//                          spin on done[kb] before starting.
// x:      [16384, 4096] fp32, logical [tokens, 8, 512]
// blocks: [8, 512, 512] fp32 [k][n] -> pre-transposed fp16 [n][k] scratch g_bt16
// out[m, kb*512+n] = sum_k x[m, kb*512+k] * blocks[kb, k, n]

#define HIDDEN 4096
#define BLKD   512
#define NB     8
#define BM     128
#define BN     128
#define BK     64            // 64 halves = 128 B per smem row
#define NITER  (BLKD / BK)   // 8
#define NTH    256
#define STAGES 3
#define NCONV  256           // converter CTAs (must be <= wave-1 residency)
#define MTOK   16384         // tokens (fixed shape)

#define ABYTES (BM * BK * 2)             // 16384
#define BBYTES (BN * BK * 2)             // 16384
#define BUFBYTES (ABYTES + BBYTES)       // 32768
#define SMEM_BYTES (STAGES * BUFBYTES)   // 98304

__device__ __half g_xh[MTOK * HIDDEN];       // 134 MB fp16 x
__device__ __half g_bt16[NB * BLKD * BLKD];  // 4 MB, [kb][n][k]
__device__ int    g_done[NB];                // slab-ready counters

#define SWZ(o) ((o) ^ (((o) >> 3) & 0x70))

static __device__ __forceinline__ uint32_t smem_u32(const void* p) {
    uint32_t a;
    asm("{ .reg .u64 t; cvta.to.shared.u64 t, %1; cvt.u32.u64 %0, t; }"
        : "=r"(a) : "l"(p));
    return a;
}

#define LDSM4(r0, r1, r2, r3, addr)                                          \
    asm volatile("ldmatrix.sync.aligned.m8n8.x4.shared.b16 {%0,%1,%2,%3}, [%4];" \
                 : "=r"(r0), "=r"(r1), "=r"(r2), "=r"(r3) : "r"(addr))

#define MMA_F16(c, a, b)                                                     \
    asm volatile("mma.sync.aligned.m16n8k16.row.col.f32.f16.f16.f32 "        \
                 "{%0,%1,%2,%3}, {%4,%5,%6,%7}, {%8,%9}, {%0,%1,%2,%3};"     \
                 : "+f"((c)[0]), "+f"((c)[1]), "+f"((c)[2]), "+f"((c)[3])    \
                 : "r"((a)[0]), "r"((a)[1]), "r"((a)[2]), "r"((a)[3]),       \
                   "r"((b)[0]), "r"((b)[1]))

#define CPASYNC16(dst, src)                                                  \
    asm volatile("cp.async.cg.shared.global [%0], [%1], 16;"                 \
                 :: "r"(dst), "l"(src) : "memory")

// ---------------- pre-pass: B transpose/convert + flag reset ----------------
__global__ void prep_b_kernel(const float* __restrict__ blocks) {
    __shared__ float tile[32][33];
    const int kb = blockIdx.z;
    const int k0 = blockIdx.x * 32, n0 = blockIdx.y * 32;
    const int tx = threadIdx.x, ty = threadIdx.y;  // 32 x 8
    if (blockIdx.x == 0 && blockIdx.y == 0 && tx == 0 && ty == 0)
        g_done[kb] = 0;   // reset slab counter for this launch (graph-replay safe)
    #pragma unroll
    for (int i = 0; i < 32; i += 8)
        tile[ty + i][tx] = blocks[(size_t)kb * BLKD * BLKD + (size_t)(k0 + ty + i) * BLKD + n0 + tx];
    __syncthreads();
    #pragma unroll
    for (int i = 0; i < 32; i += 8)
        g_bt16[(size_t)kb * BLKD * BLKD + (size_t)(n0 + ty + i) * BLKD + k0 + tx] =
            __float2half_rn(tile[tx][ty + i]);
}

// ---------------- fused converter + GEMM ----------------
__global__ __launch_bounds__(NTH, 2)
void tpt_fused_kernel(const float* __restrict__ x, float* __restrict__ out) {
    const int bid = blockIdx.x;
    const int tid = threadIdx.x;

    if (bid < NCONV) {
        // ============ CONVERTER: x fp32 -> fp16, slab kb at a time ============
        // slab kb: 16384 rows x 512 cols; 8-float units: 16384*512/8 = 1,048,576
        const int stride = NCONV * NTH;           // 65536 units/sweep
        #pragma unroll 1
        for (int kb = 0; kb < NB; kb++) {
            const float* xs = x + (size_t)kb * BLKD;
            __half* dst = g_xh + (size_t)kb * BLKD;
            #pragma unroll 1
            for (int i = bid * NTH + tid; i < (MTOK * BLKD) / 8; i += stride) {
                const int row = i >> 6;           // 64 units of 8 per row
                const int col = (i & 63) * 8;     // fp32 col within slab
                const float4* src = reinterpret_cast<const float4*>(
                    xs + (size_t)row * HIDDEN + col);
                float4 v0 = src[0], v1 = src[1];
                __half2 h0 = __floats2half2_rn(v0.x, v0.y);
                __half2 h1 = __floats2half2_rn(v0.z, v0.w);
                __half2 h2 = __floats2half2_rn(v1.x, v1.y);
                __half2 h3 = __floats2half2_rn(v1.z, v1.w);
                uint4 o;
                o.x = *reinterpret_cast<uint32_t*>(&h0);
                o.y = *reinterpret_cast<uint32_t*>(&h1);
                o.z = *reinterpret_cast<uint32_t*>(&h2);
                o.w = *reinterpret_cast<uint32_t*>(&h3);
                *reinterpret_cast<uint4*>(dst + (size_t)row * HIDDEN + col) = o;
            }
            __syncthreads();
            if (tid == 0) {
                __threadfence();                  // publish slab writes
                atomicAdd(&g_done[kb], 1);
            }
        }
        return;
    }

    // ============ GEMM (R5 config, kb-major CTA order) ============
    const int gb  = bid - NCONV;          // 0..4095
    const int kb  = gb >> 9;              // 512 CTAs per block: 128 mtiles x 4 ntiles
    const int rem = gb & 511;
    const int n0  = (rem & 3) * BN;       // n fastest: A-sharing CTAs adjacent
    const int m0  = (rem >> 2) * BM;

    // wait for slab kb converted
    if (tid == 0) {
        while (atomicAdd(&g_done[kb], 0) < NCONV)
            __nanosleep(200);
        __threadfence();                  // acquire
    }
    __syncthreads();

    extern __shared__ __align__(1024) char smem[];
    const uint32_t sbase = smem_u32(smem);
    const int wid = tid >> 5, l = tid & 31;
    const int wm0 = (wid & 1) * 64;
    const int wn0 = (wid >> 1) * 32;

    const int q = tid & 7;
    const int rbase = tid >> 3;
    const uint32_t stg_swz = SWZ((uint32_t)(rbase * 128 + q * 16));  // +j*4096 safe

    const __half* Ag = g_xh + (size_t)(m0 + rbase) * HIDDEN + kb * BLKD + q * 8;
    const __half* Bg = g_bt16 + (size_t)kb * BLKD * BLKD + (size_t)(n0 + rbase) * BLKD + q * 8;

    float acc[4][4][4];
    #pragma unroll
    for (int mi = 0; mi < 4; mi++)
        #pragma unroll
        for (int nt = 0; nt < 4; nt++)
            #pragma unroll
            for (int r = 0; r < 4; r++) acc[mi][nt][r] = 0.0f;

    const int mat = l >> 3;
    const int r8  = l & 7;
    const int a_rowadd = (mat & 1) * 8 + r8;
    const int a_colb   = (mat >> 1) * 16;
    const int b_rowadd = (mat >> 1) * 8 + r8;
    const int b_colb   = (mat & 1) * 16;

    auto issue_stage = [&](int kt) {
        const uint32_t buf = sbase + (uint32_t)(kt % STAGES) * BUFBYTES;
        const __half* asrc = Ag + (size_t)kt * BK;
        const __half* bsrc = Bg + (size_t)kt * BK;
        #pragma unroll
        for (int i = 0; i < 4; i++)
            CPASYNC16(buf + stg_swz + i * 4096u, asrc + (size_t)i * 32 * HIDDEN);
        #pragma unroll
        for (int i = 0; i < 4; i++)
            CPASYNC16(buf + ABYTES + stg_swz + i * 4096u, bsrc + (size_t)i * 32 * BLKD);
        asm volatile("cp.async.commit_group;" ::: "memory");
    };

    issue_stage(0);
    issue_stage(1);

    #pragma unroll 1
    for (int kt = 0; kt < NITER; kt++) {
        if (kt + 1 < NITER) {
            asm volatile("cp.async.wait_group 1;" ::: "memory");
        } else {
            asm volatile("cp.async.wait_group 0;" ::: "memory");
        }
        __syncthreads();

        if (kt + 2 < NITER) issue_stage(kt + 2);

        const uint32_t abase = sbase + (uint32_t)(kt % STAGES) * BUFBYTES;
        const uint32_t bbase = abase + ABYTES;
        #pragma unroll
        for (int ks = 0; ks < 4; ks++) {          // 4 x k16 steps (BK=64)
            uint32_t aF[4][4], bF[4][2];
            #pragma unroll
            for (int mi = 0; mi < 4; mi++) {
                uint32_t off = (uint32_t)((wm0 + mi * 16 + a_rowadd) * 128 + a_colb + ks * 32);
                LDSM4(aF[mi][0], aF[mi][1], aF[mi][2], aF[mi][3], abase + SWZ(off));
            }
            #pragma unroll
            for (int p = 0; p < 2; p++) {
                uint32_t off = (uint32_t)((wn0 + p * 16 + b_rowadd) * 128 + b_colb + ks * 32);
                LDSM4(bF[2 * p][0], bF[2 * p][1], bF[2 * p + 1][0], bF[2 * p + 1][1],
                      bbase + SWZ(off));
            }
            #pragma unroll
            for (int mi = 0; mi < 4; mi++)
                #pragma unroll
                for (int nt = 0; nt < 4; nt++)
                    MMA_F16(acc[mi][nt], aF[mi], bF[nt]);
        }
    }

    // ---- epilogue: direct float2 stores ----
    #pragma unroll
    for (int mi = 0; mi < 4; mi++) {
        const int grow = m0 + wm0 + mi * 16 + (l >> 2);
        #pragma unroll
        for (int nt = 0; nt < 4; nt++) {
            const int gcol = kb * BLKD + n0 + wn0 + nt * 8 + 2 * (l & 3);
            float2 v01 = make_float2(acc[mi][nt][0], acc[mi][nt][1]);
            float2 v23 = make_float2(acc[mi][nt][2], acc[mi][nt][3]);
            *reinterpret_cast<float2*>(out + (size_t)grow * HIDDEN + gcol) = v01;
            *reinterpret_cast<float2*>(out + (size_t)(grow + 8) * HIDDEN + gcol) = v23;
        }
    }
}

extern "C" void kernel_launch(void* const* d_in, const int* in_sizes, int n_in,
                              void* d_out, int out_size) {
    const float* x      = (const float*)d_in[0];
    const float* blocks = (const float*)d_in[1];
    float*       out    = (float*)d_out;

    const int M = in_sizes[0] / HIDDEN;  // 16384

    cudaFuncSetAttribute(tpt_fused_kernel,
                         cudaFuncAttributeMaxDynamicSharedMemorySize, SMEM_BYTES);

    dim3 gp(BLKD / 32, BLKD / 32, NB), bp(32, 8);
    prep_b_kernel<<<gp, bp>>>(blocks);   // also resets g_done[] (stream-ordered)

    const int gemm_ctas = (M / BM) * (BLKD / BN) * NB;  // 4096
    tpt_fused_kernel<<<NCONV + gemm_ctas, NTH, SMEM_BYTES>>>(x, out);
}

// round 15
// speedup vs baseline: 1.1790x; 1.1790x over previous
#include <cuda_runtime.h>
#include <cuda_fp16.h>
#include <cstdint>

// Block-diagonal GEMM: self-converting GEMM CTAs (no dedicated converters).
// 4 sibling CTAs per A-tile (same kb, mtile; ntile 0..3) each convert 32 rows of
// the tile fp32->fp16 into g_xh, sync via per-tile counter, then run the R5
// 128x128 fp16 mma.sync mainloop.
// x:      [16384, 4096] fp32, logical [tokens, 8, 512]
// blocks: [8, 512, 512] fp32 [k][n] -> pre-transposed fp16 [n][k] scratch g_bt16
// out[m, kb*512+n] = sum_k x[m, kb*512+k] * blocks[kb, k, n]

#define HIDDEN 4096
#define BLKD   512
#define NB     8
#define BM     128
#define BN     128
#define BK     64            // 64 halves = 128 B per smem row
#define NITER  (BLKD / BK)   // 8
#define NTH    256
#define STAGES 3
#define NMT    128           // m-tiles

#define ABYTES (BM * BK * 2)             // 16384
#define BBYTES (BN * BK * 2)             // 16384
#define BUFBYTES (ABYTES + BBYTES)       // 32768
#define SMEM_BYTES (STAGES * BUFBYTES)   // 98304

__device__ __half g_xh[16384 * HIDDEN];      // 134 MB fp16 x
__device__ __half g_bt16[NB * BLKD * BLKD];  // 4 MB, [kb][n][k]
__device__ int    g_flag[NB * NMT];          // per-(kb, mtile) ready counters (0..4)

#define SWZ(o) ((o) ^ (((o) >> 3) & 0x70))

static __device__ __forceinline__ uint32_t smem_u32(const void* p) {
    uint32_t a;
    asm("{ .reg .u64 t; cvta.to.shared.u64 t, %1; cvt.u32.u64 %0, t; }"
        : "=r"(a) : "l"(p));
    return a;
}

#define LDSM4(r0, r1, r2, r3, addr)                                          \
    asm volatile("ldmatrix.sync.aligned.m8n8.x4.shared.b16 {%0,%1,%2,%3}, [%4];" \
                 : "=r"(r0), "=r"(r1), "=r"(r2), "=r"(r3) : "r"(addr))

#define MMA_F16(c, a, b)                                                     \
    asm volatile("mma.sync.aligned.m16n8k16.row.col.f32.f16.f16.f32 "        \
                 "{%0,%1,%2,%3}, {%4,%5,%6,%7}, {%8,%9}, {%0,%1,%2,%3};"     \
                 : "+f"((c)[0]), "+f"((c)[1]), "+f"((c)[2]), "+f"((c)[3])    \
                 : "r"((a)[0]), "r"((a)[1]), "r"((a)[2]), "r"((a)[3]),       \
                   "r"((b)[0]), "r"((b)[1]))

#define CPASYNC16(dst, src)                                                  \
    asm volatile("cp.async.cg.shared.global [%0], [%1], 16;"                 \
                 :: "r"(dst), "l"(src) : "memory")

// ---------------- pre-pass: B transpose/convert + flag reset ----------------
__global__ void prep_b_kernel(const float* __restrict__ blocks) {
    __shared__ float tile[32][33];
    const int kb = blockIdx.z;
    const int k0 = blockIdx.x * 32, n0 = blockIdx.y * 32;
    const int tx = threadIdx.x, ty = threadIdx.y;  // 32 x 8
    const int t = ty * 32 + tx;
    if (blockIdx.x == 0 && blockIdx.y == 0 && t < NMT)
        g_flag[kb * NMT + t] = 0;   // reset tile counters (graph-replay safe)
    #pragma unroll
    for (int i = 0; i < 32; i += 8)
        tile[ty + i][tx] = blocks[(size_t)kb * BLKD * BLKD + (size_t)(k0 + ty + i) * BLKD + n0 + tx];
    __syncthreads();
    #pragma unroll
    for (int i = 0; i < 32; i += 8)
        g_bt16[(size_t)kb * BLKD * BLKD + (size_t)(n0 + ty + i) * BLKD + k0 + tx] =
            __float2half_rn(tile[tx][ty + i]);
}

// ---------------- fused self-converting GEMM ----------------
__global__ __launch_bounds__(NTH, 2)
void tpt_fused_kernel(const float* __restrict__ x, float* __restrict__ out) {
    const int bid = blockIdx.x;
    const int tid = threadIdx.x;

    // CTA mapping: kb-major, then mtile, n fastest (siblings bid-adjacent)
    const int kb  = bid >> 9;             // 512 CTAs per kb
    const int rem = bid & 511;
    const int nq  = rem & 3;              // n-tile index = conversion quarter
    const int mt  = rem >> 2;
    const int n0  = nq * BN;
    const int m0  = mt * BM;
    int* flag = &g_flag[kb * NMT + mt];

    // ---- pre-phase: convert 32 rows [m0 + nq*32, +32) of slab kb ----
    {
        const float* xs = x + (size_t)(m0 + nq * 32) * HIDDEN + kb * BLKD;
        __half* dst = g_xh + (size_t)(m0 + nq * 32) * HIDDEN + kb * BLKD;
        // 32 rows x 512 cols = 2048 units of 8 floats; 256 threads x 8 units
        #pragma unroll
        for (int j = 0; j < 8; j++) {
            const int u = tid + j * 256;
            const int row = u >> 6;           // 64 units per row
            const int col = (u & 63) * 8;
            const float4* src = reinterpret_cast<const float4*>(
                xs + (size_t)row * HIDDEN + col);
            float4 v0 = src[0], v1 = src[1];
            __half2 h0 = __floats2half2_rn(v0.x, v0.y);
            __half2 h1 = __floats2half2_rn(v0.z, v0.w);
            __half2 h2 = __floats2half2_rn(v1.x, v1.y);
            __half2 h3 = __floats2half2_rn(v1.z, v1.w);
            uint4 o;
            o.x = *reinterpret_cast<uint32_t*>(&h0);
            o.y = *reinterpret_cast<uint32_t*>(&h1);
            o.z = *reinterpret_cast<uint32_t*>(&h2);
            o.w = *reinterpret_cast<uint32_t*>(&h3);
            *reinterpret_cast<uint4*>(dst + (size_t)row * HIDDEN + col) = o;
        }
        __threadfence();        // publish this thread's quarter-tile writes
        __syncthreads();        // all threads' fences done
        if (tid == 0) atomicAdd(flag, 1);
        // wait for all 4 quarters
        if (tid == 0) {
            while (atomicAdd(flag, 0) < 4)
                __nanosleep(100);
            __threadfence();    // acquire
        }
        __syncthreads();
    }

    // ---- R5 GEMM mainloop (unchanged) ----
    extern __shared__ __align__(1024) char smem[];
    const uint32_t sbase = smem_u32(smem);
    const int wid = tid >> 5, l = tid & 31;
    const int wm0 = (wid & 1) * 64;
    const int wn0 = (wid >> 1) * 32;

    const int q = tid & 7;
    const int rbase = tid >> 3;
    const uint32_t stg_swz = SWZ((uint32_t)(rbase * 128 + q * 16));  // +j*4096 safe

    const __half* Ag = g_xh + (size_t)(m0 + rbase) * HIDDEN + kb * BLKD + q * 8;
    const __half* Bg = g_bt16 + (size_t)kb * BLKD * BLKD + (size_t)(n0 + rbase) * BLKD + q * 8;

    float acc[4][4][4];
    #pragma unroll
    for (int mi = 0; mi < 4; mi++)
        #pragma unroll
        for (int nt = 0; nt < 4; nt++)
            #pragma unroll
            for (int r = 0; r < 4; r++) acc[mi][nt][r] = 0.0f;

    const int mat = l >> 3;
    const int r8  = l & 7;
    const int a_rowadd = (mat & 1) * 8 + r8;
    const int a_colb   = (mat >> 1) * 16;
    const int b_rowadd = (mat >> 1) * 8 + r8;
    const int b_colb   = (mat & 1) * 16;

    auto issue_stage = [&](int kt) {
        const uint32_t buf = sbase + (uint32_t)(kt % STAGES) * BUFBYTES;
        const __half* asrc = Ag + (size_t)kt * BK;
        const __half* bsrc = Bg + (size_t)kt * BK;
        #pragma unroll
        for (int i = 0; i < 4; i++)
            CPASYNC16(buf + stg_swz + i * 4096u, asrc + (size_t)i * 32 * HIDDEN);
        #pragma unroll
        for (int i = 0; i < 4; i++)
            CPASYNC16(buf + ABYTES + stg_swz + i * 4096u, bsrc + (size_t)i * 32 * BLKD);
        asm volatile("cp.async.commit_group;" ::: "memory");
    };

    issue_stage(0);
    issue_stage(1);

    #pragma unroll 1
    for (int kt = 0; kt < NITER; kt++) {
        if (kt + 1 < NITER) {
            asm volatile("cp.async.wait_group 1;" ::: "memory");
        } else {
            asm volatile("cp.async.wait_group 0;" ::: "memory");
        }
        __syncthreads();

        if (kt + 2 < NITER) issue_stage(kt + 2);

        const uint32_t abase = sbase + (uint32_t)(kt % STAGES) * BUFBYTES;
        const uint32_t bbase = abase + ABYTES;
        #pragma unroll
        for (int ks = 0; ks < 4; ks++) {          // 4 x k16 steps (BK=64)
            uint32_t aF[4][4], bF[4][2];
            #pragma unroll
            for (int mi = 0; mi < 4; mi++) {
                uint32_t off = (uint32_t)((wm0 + mi * 16 + a_rowadd) * 128 + a_colb + ks * 32);
                LDSM4(aF[mi][0], aF[mi][1], aF[mi][2], aF[mi][3], abase + SWZ(off));
            }
            #pragma unroll
            for (int p = 0; p < 2; p++) {
                uint32_t off = (uint32_t)((wn0 + p * 16 + b_rowadd) * 128 + b_colb + ks * 32);
                LDSM4(bF[2 * p][0], bF[2 * p][1], bF[2 * p + 1][0], bF[2 * p + 1][1],
                      bbase + SWZ(off));
            }
            #pragma unroll
            for (int mi = 0; mi < 4; mi++)
                #pragma unroll
                for (int nt = 0; nt < 4; nt++)
                    MMA_F16(acc[mi][nt], aF[mi], bF[nt]);
        }
    }

    // ---- epilogue: direct float2 stores ----
    #pragma unroll
    for (int mi = 0; mi < 4; mi++) {
        const int grow = m0 + wm0 + mi * 16 + (l >> 2);
        #pragma unroll
        for (int nt = 0; nt < 4; nt++) {
            const int gcol = kb * BLKD + n0 + wn0 + nt * 8 + 2 * (l & 3);
            float2 v01 = make_float2(acc[mi][nt][0], acc[mi][nt][1]);
            float2 v23 = make_float2(acc[mi][nt][2], acc[mi][nt][3]);
            *reinterpret_cast<float2*>(out + (size_t)grow * HIDDEN + gcol) = v01;
            *reinterpret_cast<float2*>(out + (size_t)(grow + 8) * HIDDEN + gcol) = v23;
        }
    }
}

extern "C" void kernel_launch(void* const* d_in, const int* in_sizes, int n_in,
                              void* d_out, int out_size) {
    const float* x      = (const float*)d_in[0];
    const float* blocks = (const float*)d_in[1];
    float*       out    = (float*)d_out;

    const int M = in_sizes[0] / HIDDEN;  // 16384

    cudaFuncSetAttribute(tpt_fused_kernel,
                         cudaFuncAttributeMaxDynamicSharedMemorySize, SMEM_BYTES);

    dim3 gp(BLKD / 32, BLKD / 32, NB), bp(32, 8);
    prep_b_kernel<<<gp, bp>>>(blocks);   // also resets g_flag[] (stream-ordered)

    const int gemm_ctas = (M / BM) * (BLKD / BN) * NB;  // 4096
    tpt_fused_kernel<<<gemm_ctas, NTH, SMEM_BYTES>>>(x, out);
}